// round 5
// baseline (speedup 1.0000x reference)
#include <cuda_runtime.h>
#include <cuda_bf16.h>
#include <cstdint>

namespace {
constexpr int T_STEPS = 512;
constexpr int TILE_B  = 16;
constexpr int THREADS = 256;
constexpr int GRID    = 2048 / TILE_B;

constexpr int OFF_A1H = 0;
constexpr int OFF_A1L = 32768;
constexpr int OFF_A2H = 65536;
constexpr int OFF_A2L = 131072;
constexpr int OFF_HH  = 196608;
constexpr int OFF_HL  = 196608 + 4352;
constexpr int OFF_X   = 196608 + 8704;
constexpr int SMEM_TOTAL = OFF_X + 4096;   // 209408 B
constexpr int HS = 136;                    // bf16 per h row (conflict-free pad)

__device__ __forceinline__ uint32_t smem_u32(const void* p) {
  uint32_t a;
  asm("{ .reg .u64 t; cvta.to.shared.u64 t, %1; cvt.u32.u64 %0, t; }" : "=r"(a) : "l"(p));
  return a;
}
__device__ __forceinline__ void ldm4(uint32_t* r, uint32_t a) {
  asm volatile("ldmatrix.sync.aligned.m8n8.x4.shared.b16 {%0,%1,%2,%3}, [%4];"
               : "=r"(r[0]), "=r"(r[1]), "=r"(r[2]), "=r"(r[3]) : "r"(a));
}
__device__ __forceinline__ void mma_bf(float4& d, const uint4& a, uint32_t b0, uint32_t b1) {
  asm volatile("mma.sync.aligned.m16n8k16.row.col.f32.bf16.bf16.f32 "
               "{%0,%1,%2,%3}, {%4,%5,%6,%7}, {%8,%9}, {%0,%1,%2,%3};"
               : "+f"(d.x), "+f"(d.y), "+f"(d.z), "+f"(d.w)
               : "r"(a.x), "r"(a.y), "r"(a.z), "r"(a.w), "r"(b0), "r"(b1));
}
__device__ __forceinline__ uint32_t pkbf2(float lo, float hi) {
  __nv_bfloat16 l = __float2bfloat16(lo), h = __float2bfloat16(hi);
  unsigned short ls, hs;
  memcpy(&ls, &l, 2); memcpy(&hs, &h, 2);
  return (uint32_t)ls | ((uint32_t)hs << 16);
}
__device__ __forceinline__ float sigf(float v) {
  return __fdividef(1.0f, 1.0f + __expf(-v));
}
__device__ __forceinline__ float tanhfa(float v) {
  return 2.0f * __fdividef(1.0f, 1.0f + __expf(-2.0f * v)) - 1.0f;
}
__device__ __forceinline__ void gbar(int id) {
  asm volatile("bar.sync %0, 128;" :: "r"(id) : "memory");
}
}  // namespace

__global__ void __launch_bounds__(THREADS, 1) lstm2_hmma2g_kernel(
    const float* __restrict__ x,
    const float* __restrict__ Wih0, const float* __restrict__ Whh0,
    const float* __restrict__ bih0, const float* __restrict__ bhh0,
    const float* __restrict__ Wih1, const float* __restrict__ Whh1,
    const float* __restrict__ bih1, const float* __restrict__ bhh1,
    const float* __restrict__ fcW,  const float* __restrict__ fcb,
    float* __restrict__ out)
{
  extern __shared__ char sm[];
  const uint32_t sb = smem_u32(sm);
  const int tid = threadIdx.x, warp = tid >> 5, lane = tid & 31;
  const int Gp = warp >> 2;         // batch group (0,1): batches 8*Gp..+8
  const int wg = warp & 2 ? (warp & 3) : (warp & 3);  // warp-in-group 0..3
  const int wig = warp & 3;
  const int p = lane >> 2, c = lane & 3;
  const int barid = Gp + 1;
  const int bBase = blockIdx.x * TILE_B;
  (void)wg;

  // ---- build A fragments: warp wig covers rows [64*wig, 64*wig+64),
  // row R = 64*wig + g*16 + q*8 + p  <->  gate g, unit u = 16*wig + 8*q + p ----
  for (int i = tid; i < 64 * 32; i += THREADS) {
    int fi = i >> 5, l = i & 31;
    int fw = fi >> 4, g = (fi >> 2) & 3, kc = fi & 3;
    int lp = l >> 2, c0 = (l & 3) * 2;
    float wh[8], wl[8];
#pragma unroll
    for (int e = 0; e < 8; ++e) {
      int q = (e >> 1) & 1;
      int k = kc * 16 + c0 + (e & 1) + (e >> 2) * 8;
      int u = 16 * fw + 8 * q + lp;
      float wv = Whh0[(g * 64 + u) * 64 + k];
      __nv_bfloat16 b = __float2bfloat16(wv);
      wh[e] = __bfloat162float(b); wl[e] = wv - wh[e];
    }
    *(uint4*)(sm + OFF_A1H + (size_t)i * 16) =
        make_uint4(pkbf2(wh[0],wh[1]), pkbf2(wh[2],wh[3]), pkbf2(wh[4],wh[5]), pkbf2(wh[6],wh[7]));
    *(uint4*)(sm + OFF_A1L + (size_t)i * 16) =
        make_uint4(pkbf2(wl[0],wl[1]), pkbf2(wl[2],wl[3]), pkbf2(wl[4],wl[5]), pkbf2(wl[6],wl[7]));
  }
  for (int i = tid; i < 128 * 32; i += THREADS) {
    int fi = i >> 5, l = i & 31;
    int fw = fi >> 5, g = (fi >> 3) & 3, kc = fi & 7;
    int lp = l >> 2, c0 = (l & 3) * 2;
    float wh[8], wl[8];
#pragma unroll
    for (int e = 0; e < 8; ++e) {
      int q = (e >> 1) & 1;
      int k = kc * 16 + c0 + (e & 1) + (e >> 2) * 8;
      int u = 16 * fw + 8 * q + lp;
      float wv = (k < 64) ? Wih1[(g * 64 + u) * 64 + k]
                          : Whh1[(g * 64 + u) * 64 + (k - 64)];
      __nv_bfloat16 b = __float2bfloat16(wv);
      wh[e] = __bfloat162float(b); wl[e] = wv - wh[e];
    }
    *(uint4*)(sm + OFF_A2H + (size_t)i * 16) =
        make_uint4(pkbf2(wh[0],wh[1]), pkbf2(wh[2],wh[3]), pkbf2(wh[4],wh[5]), pkbf2(wh[6],wh[7]));
    *(uint4*)(sm + OFF_A2L + (size_t)i * 16) =
        make_uint4(pkbf2(wl[0],wl[1]), pkbf2(wl[2],wl[3]), pkbf2(wl[4],wl[5]), pkbf2(wl[6],wl[7]));
  }
  for (int i = tid; i < 2176; i += THREADS)
    reinterpret_cast<uint32_t*>(sm + OFF_HH)[i] = 0u;

  // per-thread act constants: 2 units (q=0,1), 4 gates
  float wx[2][4], b0c[2][4], b1c[2][4];
#pragma unroll
  for (int q = 0; q < 2; ++q) {
    int u = 16 * wig + 8 * q + p;
#pragma unroll
    for (int g = 0; g < 4; ++g) {
      wx[q][g]  = Wih0[g * 64 + u];
      b0c[q][g] = bih0[g * 64 + u] + bhh0[g * 64 + u];
      b1c[q][g] = bih1[g * 64 + u] + bhh1[g * 64 + u];
    }
  }

  // ldmatrix per-lane base: tile ti covers (kcPair-sub, k-half)
  const int ti = lane >> 3;
  const uint32_t nrow = 8 * Gp + (lane & 7);
  const uint32_t colb = (uint32_t)((ti >> 1) * 16 + (ti & 1) * 8);
  const uint32_t bHH = sb + OFF_HH + (nrow * HS + colb) * 2;
  const uint32_t bHL = sb + OFF_HL + (nrow * HS + colb) * 2;

  float* xb = reinterpret_cast<float*>(sm + OFF_X);
  float c1[2][2] = {{0.f,0.f},{0.f,0.f}}, c2[2][2] = {{0.f,0.f},{0.f,0.f}};

  // B fragments: Bh1/Bl1 = h1 (cols 0-63, kc0-3) persist across iterations
  uint32_t Bh1[4][2], Bl1[4][2], Bh2[4][2], Bl2[4][2];
#pragma unroll
  for (int kc = 0; kc < 4; ++kc)
    Bh1[kc][0] = Bh1[kc][1] = Bl1[kc][0] = Bl1[kc][1] = 0u;   // h1(-1)=0

  __syncthreads();

  const int ttg = tid & 127;

  for (int t = 0; t < T_STEPS; ++t) {
    if ((t & 63) == 0) {
      // group stages its 8 batches x 64 timesteps of x (transposed)
      int b8 = ttg >> 4, tq = ttg & 15;
      float4 v = *reinterpret_cast<const float4*>(
          x + (size_t)(bBase + 8 * Gp + b8) * T_STEPS + t + tq * 4);
      int nn = 8 * Gp + b8;
      xb[(tq * 4 + 0) * 16 + nn] = v.x;
      xb[(tq * 4 + 1) * 16 + nn] = v.y;
      xb[(tq * 4 + 2) * 16 + nn] = v.z;
      xb[(tq * 4 + 3) * 16 + nn] = v.w;
      gbar(barid);
    }

    // phase0: load h2(t-1) frags (cols 64-127 -> kc4-7, pairs P=2,3)
    {
      uint32_t r[4];
      ldm4(r, bHH + 128); Bh2[0][0]=r[0]; Bh2[0][1]=r[1]; Bh2[1][0]=r[2]; Bh2[1][1]=r[3];
      ldm4(r, bHH + 192); Bh2[2][0]=r[0]; Bh2[2][1]=r[1]; Bh2[3][0]=r[2]; Bh2[3][1]=r[3];
      ldm4(r, bHL + 128); Bl2[0][0]=r[0]; Bl2[0][1]=r[1]; Bl2[1][0]=r[2]; Bl2[1][1]=r[3];
      ldm4(r, bHL + 192); Bl2[2][0]=r[0]; Bl2[2][1]=r[1]; Bl2[3][0]=r[2]; Bl2[3][1]=r[3];
    }

    // ===== GEMM1: gates1(t) = W1 * h1(t-1)  (Bh1/Bl1 from prev iter) =====
    float4 D[4];
#pragma unroll
    for (int g = 0; g < 4; ++g) D[g] = make_float4(0.f,0.f,0.f,0.f);
#pragma unroll
    for (int kc = 0; kc < 4; ++kc)
#pragma unroll
      for (int g = 0; g < 4; ++g) {
        uint4 ah = *(const uint4*)(sm + OFF_A1H + (size_t)(((wig*16 + g*4 + kc)*32) + lane)*16);
        uint4 al = *(const uint4*)(sm + OFF_A1L + (size_t)(((wig*16 + g*4 + kc)*32) + lane)*16);
        mma_bf(D[g], ah, Bh1[kc][0], Bh1[kc][1]);
        mma_bf(D[g], ah, Bl1[kc][0], Bl1[kc][1]);
        mma_bf(D[g], al, Bh1[kc][0], Bh1[kc][1]);
      }

    // ----- act1 -> h1(t) (cols 0-63, group rows) -----
#pragma unroll
    for (int q = 0; q < 2; ++q)
#pragma unroll
      for (int j = 0; j < 2; ++j) {
        int n = 8 * Gp + 2 * c + j;
        int u = 16 * wig + 8 * q + p;
        float xv = xb[(t & 63) * 16 + n];
        const int di = q * 2 + j;
        float gi = ((const float*)&D[0])[di] + b0c[q][0] + wx[q][0] * xv;
        float gf = ((const float*)&D[1])[di] + b0c[q][1] + wx[q][1] * xv;
        float gg = ((const float*)&D[2])[di] + b0c[q][2] + wx[q][2] * xv;
        float go = ((const float*)&D[3])[di] + b0c[q][3] + wx[q][3] * xv;
        float cn = sigf(gf) * c1[q][j] + sigf(gi) * tanhfa(gg);
        c1[q][j] = cn;
        float h = sigf(go) * tanhfa(cn);
        __nv_bfloat16 hhv = __float2bfloat16(h);
        *(__nv_bfloat16*)(sm + OFF_HH + (size_t)(n * HS + u) * 2) = hhv;
        *(__nv_bfloat16*)(sm + OFF_HL + (size_t)(n * HS + u) * 2) =
            __float2bfloat16(h - __bfloat162float(hhv));
      }
    gbar(barid);   // h1(t) visible to group

    // phase2: load h1(t) frags (cols 0-63, pairs P=0,1) -> reused next iter
    {
      uint32_t r[4];
      ldm4(r, bHH + 0);  Bh1[0][0]=r[0]; Bh1[0][1]=r[1]; Bh1[1][0]=r[2]; Bh1[1][1]=r[3];
      ldm4(r, bHH + 64); Bh1[2][0]=r[0]; Bh1[2][1]=r[1]; Bh1[3][0]=r[2]; Bh1[3][1]=r[3];
      ldm4(r, bHL + 0);  Bl1[0][0]=r[0]; Bl1[0][1]=r[1]; Bl1[1][0]=r[2]; Bl1[1][1]=r[3];
      ldm4(r, bHL + 64); Bl1[2][0]=r[0]; Bl1[2][1]=r[1]; Bl1[3][0]=r[2]; Bl1[3][1]=r[3];
    }

    // ===== GEMM2: gates2(t) = W2 * [h1(t); h2(t-1)] =====
#pragma unroll
    for (int g = 0; g < 4; ++g) D[g] = make_float4(0.f,0.f,0.f,0.f);
#pragma unroll
    for (int kc = 0; kc < 8; ++kc) {
      const uint32_t* bh = (kc < 4) ? Bh1[kc] : Bh2[kc - 4];
      const uint32_t* bl = (kc < 4) ? Bl1[kc] : Bl2[kc - 4];
#pragma unroll
      for (int g = 0; g < 4; ++g) {
        uint4 ah = *(const uint4*)(sm + OFF_A2H + (size_t)(((wig*32 + g*8 + kc)*32) + lane)*16);
        uint4 al = *(const uint4*)(sm + OFF_A2L + (size_t)(((wig*32 + g*8 + kc)*32) + lane)*16);
        mma_bf(D[g], ah, bh[0], bh[1]);
        mma_bf(D[g], ah, bl[0], bl[1]);
        mma_bf(D[g], al, bh[0], bh[1]);
      }
    }

    // ----- act2 -> h2(t) (cols 64-127) -----
#pragma unroll
    for (int q = 0; q < 2; ++q)
#pragma unroll
      for (int j = 0; j < 2; ++j) {
        int n = 8 * Gp + 2 * c + j;
        int u = 16 * wig + 8 * q + p;
        const int di = q * 2 + j;
        float gi = ((const float*)&D[0])[di] + b1c[q][0];
        float gf = ((const float*)&D[1])[di] + b1c[q][1];
        float gg = ((const float*)&D[2])[di] + b1c[q][2];
        float go = ((const float*)&D[3])[di] + b1c[q][3];
        float cn = sigf(gf) * c2[q][j] + sigf(gi) * tanhfa(gg);
        c2[q][j] = cn;
        float h = sigf(go) * tanhfa(cn);
        __nv_bfloat16 hhv = __float2bfloat16(h);
        *(__nv_bfloat16*)(sm + OFF_HH + (size_t)(n * HS + 64 + u) * 2) = hhv;
        *(__nv_bfloat16*)(sm + OFF_HL + (size_t)(n * HS + 64 + u) * 2) =
            __float2bfloat16(h - __bfloat162float(hhv));
      }
    gbar(barid);   // h2(t) visible for next phase0
  }

  // ===== FC epilogue: out[b] = fcW . h2(T-1) + fcb =====
  __syncthreads();
  if (tid < TILE_B) {
    float acc = fcb[0];
    const __nv_bfloat16* hh = (const __nv_bfloat16*)(sm + OFF_HH);
    const __nv_bfloat16* hl = (const __nv_bfloat16*)(sm + OFF_HL);
#pragma unroll 8
    for (int u = 0; u < 64; ++u)
      acc += fcW[u] * (__bfloat162float(hh[tid * HS + 64 + u]) +
                       __bfloat162float(hl[tid * HS + 64 + u]));
    out[bBase + tid] = acc;
  }
}

extern "C" void kernel_launch(void* const* d_in, const int* in_sizes, int n_in,
                              void* d_out, int out_size) {
  (void)in_sizes; (void)n_in; (void)out_size;
  cudaFuncSetAttribute(lstm2_hmma2g_kernel,
                       cudaFuncAttributeMaxDynamicSharedMemorySize, SMEM_TOTAL);
  lstm2_hmma2g_kernel<<<GRID, THREADS, SMEM_TOTAL>>>(
      (const float*)d_in[0],
      (const float*)d_in[1], (const float*)d_in[2],
      (const float*)d_in[3], (const float*)d_in[4],
      (const float*)d_in[5], (const float*)d_in[6],
      (const float*)d_in[7], (const float*)d_in[8],
      (const float*)d_in[9], (const float*)d_in[10],
      (float*)d_out);
}

// round 6
// speedup vs baseline: 1.3326x; 1.3326x over previous
#include <cuda_runtime.h>
#include <cuda_bf16.h>
#include <cstdint>

namespace {
constexpr int T_STEPS = 512;
constexpr int TILE_B  = 16;
constexpr int THREADS = 256;
constexpr int GRID    = 2048 / TILE_B;

constexpr int OFF_A1H = 0;
constexpr int OFF_A1L = 32768;
constexpr int OFF_A2H = 65536;
constexpr int OFF_A2L = 131072;
constexpr int OFF_HH  = 196608;
constexpr int OFF_HL  = 196608 + 4352;
constexpr int OFF_X   = 196608 + 8704;
constexpr int SMEM_TOTAL = OFF_X + 4096;   // 209408 B
constexpr int HS = 136;                    // bf16 elems per h row (conflict-free pad)

__device__ __forceinline__ uint32_t smem_u32(const void* p) {
  uint32_t a;
  asm("{ .reg .u64 t; cvta.to.shared.u64 t, %1; cvt.u32.u64 %0, t; }" : "=r"(a) : "l"(p));
  return a;
}
__device__ __forceinline__ void ldm4(uint32_t* r, uint32_t a) {
  asm volatile("ldmatrix.sync.aligned.m8n8.x4.shared.b16 {%0,%1,%2,%3}, [%4];"
               : "=r"(r[0]), "=r"(r[1]), "=r"(r[2]), "=r"(r[3]) : "r"(a));
}
__device__ __forceinline__ void mma_bf(float4& d, const uint4& a, uint32_t b0, uint32_t b1) {
  asm volatile("mma.sync.aligned.m16n8k16.row.col.f32.bf16.bf16.f32 "
               "{%0,%1,%2,%3}, {%4,%5,%6,%7}, {%8,%9}, {%0,%1,%2,%3};"
               : "+f"(d.x), "+f"(d.y), "+f"(d.z), "+f"(d.w)
               : "r"(a.x), "r"(a.y), "r"(a.z), "r"(a.w), "r"(b0), "r"(b1));
}
__device__ __forceinline__ uint32_t pkbf2(float lo, float hi) {
  __nv_bfloat16 l = __float2bfloat16(lo), h = __float2bfloat16(hi);
  unsigned short ls, hs;
  memcpy(&ls, &l, 2); memcpy(&hs, &h, 2);
  return (uint32_t)ls | ((uint32_t)hs << 16);
}
__device__ __forceinline__ float tanh_ap(float x) {
  float y; asm("tanh.approx.f32 %0, %1;" : "=f"(y) : "f"(x)); return y;
}
__device__ __forceinline__ float sig_ap(float x) {
  return fmaf(tanh_ap(0.5f * x), 0.5f, 0.5f);
}
}  // namespace

__global__ void __launch_bounds__(THREADS, 1) lstm2_hmma3_kernel(
    const float* __restrict__ x,
    const float* __restrict__ Wih0, const float* __restrict__ Whh0,
    const float* __restrict__ bih0, const float* __restrict__ bhh0,
    const float* __restrict__ Wih1, const float* __restrict__ Whh1,
    const float* __restrict__ bih1, const float* __restrict__ bhh1,
    const float* __restrict__ fcW,  const float* __restrict__ fcb,
    float* __restrict__ out)
{
  extern __shared__ char sm[];
  const uint32_t sb = smem_u32(sm);
  const int tid = threadIdx.x, w = tid >> 5, lane = tid & 31;
  const int bBase = blockIdx.x * TILE_B;

  // ---- build A fragments (per-lane mma layout, wh/wl split), row perm:
  // mma-row R -> gate g=(R&31)>>3, unit u=(R>>5)*8+(R&7) ----
  for (int i = tid; i < 64 * 32; i += THREADS) {
    int f = i >> 5, l = i & 31;
    int mt = f >> 2, kc = f & 3;
    int p = l >> 2, c0 = (l & 3) * 2;
    float wh[8], wl[8];
#pragma unroll
    for (int e = 0; e < 8; ++e) {
      int R = mt * 16 + p + ((e >> 1) & 1) * 8;
      int k = kc * 16 + c0 + (e & 1) + (e >> 2) * 8;
      int g = (R & 31) >> 3, u = (R >> 5) * 8 + (R & 7);
      float wv = Whh0[(g * 64 + u) * 64 + k];
      __nv_bfloat16 b = __float2bfloat16(wv);
      wh[e] = __bfloat162float(b); wl[e] = wv - wh[e];
    }
    *(uint4*)(sm + OFF_A1H + (size_t)i * 16) =
        make_uint4(pkbf2(wh[0],wh[1]), pkbf2(wh[2],wh[3]), pkbf2(wh[4],wh[5]), pkbf2(wh[6],wh[7]));
    *(uint4*)(sm + OFF_A1L + (size_t)i * 16) =
        make_uint4(pkbf2(wl[0],wl[1]), pkbf2(wl[2],wl[3]), pkbf2(wl[4],wl[5]), pkbf2(wl[6],wl[7]));
  }
  for (int i = tid; i < 128 * 32; i += THREADS) {
    int f = i >> 5, l = i & 31;
    int mt = f >> 3, kc = f & 7;
    int p = l >> 2, c0 = (l & 3) * 2;
    float wh[8], wl[8];
#pragma unroll
    for (int e = 0; e < 8; ++e) {
      int R = mt * 16 + p + ((e >> 1) & 1) * 8;
      int k = kc * 16 + c0 + (e & 1) + (e >> 2) * 8;
      int g = (R & 31) >> 3, u = (R >> 5) * 8 + (R & 7);
      float wv = (k < 64) ? Wih1[(g * 64 + u) * 64 + k]
                          : Whh1[(g * 64 + u) * 64 + (k - 64)];
      __nv_bfloat16 b = __float2bfloat16(wv);
      wh[e] = __bfloat162float(b); wl[e] = wv - wh[e];
    }
    *(uint4*)(sm + OFF_A2H + (size_t)i * 16) =
        make_uint4(pkbf2(wh[0],wh[1]), pkbf2(wh[2],wh[3]), pkbf2(wh[4],wh[5]), pkbf2(wh[6],wh[7]));
    *(uint4*)(sm + OFF_A2L + (size_t)i * 16) =
        make_uint4(pkbf2(wl[0],wl[1]), pkbf2(wl[2],wl[3]), pkbf2(wl[4],wl[5]), pkbf2(wl[6],wl[7]));
  }
  // zero h buffers (hh + hl contiguous: 2*4352 B)
  for (int i = tid; i < 2176; i += THREADS)
    reinterpret_cast<uint32_t*>(sm + OFF_HH)[i] = 0u;

  // per-thread act constants: unit ut, batches n = nt*8 + (lane&3)*2 + jj
  const int ut = w * 8 + (lane >> 2);
  float wxr[4], b0r[4], b1r[4];
#pragma unroll
  for (int g = 0; g < 4; ++g) {
    wxr[g] = Wih0[g * 64 + ut];
    b0r[g] = bih0[g * 64 + ut] + bhh0[g * 64 + ut];
    b1r[g] = bih1[g * 64 + ut] + bhh1[g * 64 + ut];
  }
  // ldmatrix per-lane base: tile ti: n=((ti>>1)&1)*8+(lane&7), k=(ti&1)*8
  const int ti = lane >> 3;
  const uint32_t boff = (uint32_t)((((ti >> 1) & 1) * 8 + (lane & 7)) * HS + (ti & 1) * 8) * 2;
  const uint32_t bHH = sb + OFF_HH + boff;
  const uint32_t bHL = sb + OFF_HL + boff;

  float* xb = reinterpret_cast<float*>(sm + OFF_X);
  float c1[4] = {0.f,0.f,0.f,0.f}, c2[4] = {0.f,0.f,0.f,0.f};

  // resident h1 fragments (start at h1(-1) = 0)
  uint32_t Bh1[4][4], Bl1[4][4];
#pragma unroll
  for (int kc = 0; kc < 4; ++kc)
#pragma unroll
    for (int r = 0; r < 4; ++r) { Bh1[kc][r] = 0u; Bl1[kc][r] = 0u; }

  __syncthreads();

  for (int t = 0; t < T_STEPS; ++t) {
    if ((t & 63) == 0) {
      int b16 = tid >> 4, tq = tid & 15;
      float4 v = *reinterpret_cast<const float4*>(
          x + (size_t)(bBase + b16) * T_STEPS + t + tq * 4);
      xb[(tq * 4 + 0) * 16 + b16] = v.x;
      xb[(tq * 4 + 1) * 16 + b16] = v.y;
      xb[(tq * 4 + 2) * 16 + b16] = v.z;
      xb[(tq * 4 + 3) * 16 + b16] = v.w;
      __syncthreads();
    }

    // ---- load h2(t-1) frags (cols 64-127); disjoint from act1's writes ----
    uint32_t bh2[4][4], bl2[4][4];
#pragma unroll
    for (int kc = 0; kc < 4; ++kc) {
      ldm4(bh2[kc], bHH + 128 + kc * 32);
      ldm4(bl2[kc], bHL + 128 + kc * 32);
    }

    // ===== GEMM1: gates1 = W1 * h1(t-1), resident frags; D=main, E=comp =====
    float4 D[2][2], E[2][2];
#pragma unroll
    for (int mt = 0; mt < 2; ++mt)
#pragma unroll
      for (int nt = 0; nt < 2; ++nt) {
        D[mt][nt] = make_float4(0.f,0.f,0.f,0.f);
        E[mt][nt] = make_float4(0.f,0.f,0.f,0.f);
      }
#pragma unroll
    for (int kc = 0; kc < 4; ++kc)
#pragma unroll
      for (int mt = 0; mt < 2; ++mt) {
        uint4 ah = *(const uint4*)(sm + OFF_A1H + (size_t)(((2*w+mt)*4 + kc)*32 + lane)*16);
        uint4 al = *(const uint4*)(sm + OFF_A1L + (size_t)(((2*w+mt)*4 + kc)*32 + lane)*16);
#pragma unroll
        for (int nt = 0; nt < 2; ++nt) {
          mma_bf(D[mt][nt], ah, Bh1[kc][nt*2], Bh1[kc][nt*2+1]);
          mma_bf(E[mt][nt], ah, Bl1[kc][nt*2], Bl1[kc][nt*2+1]);
          mma_bf(E[mt][nt], al, Bh1[kc][nt*2], Bh1[kc][nt*2+1]);
        }
      }

    // ----- act1 -----
#pragma unroll
    for (int j = 0; j < 4; ++j) {
      int nt = j >> 1, jj = j & 1;
      int n  = nt * 8 + (lane & 3) * 2 + jj;
      float xv = xb[(t & 63) * 16 + n];
      float gi = (jj ? D[0][nt].y + E[0][nt].y : D[0][nt].x + E[0][nt].x) + b0r[0] + wxr[0] * xv;
      float gf = (jj ? D[0][nt].w + E[0][nt].w : D[0][nt].z + E[0][nt].z) + b0r[1] + wxr[1] * xv;
      float gg = (jj ? D[1][nt].y + E[1][nt].y : D[1][nt].x + E[1][nt].x) + b0r[2] + wxr[2] * xv;
      float go = (jj ? D[1][nt].w + E[1][nt].w : D[1][nt].z + E[1][nt].z) + b0r[3] + wxr[3] * xv;
      float cn = sig_ap(gf) * c1[j] + sig_ap(gi) * tanh_ap(gg);
      c1[j] = cn;
      float h = sig_ap(go) * tanh_ap(cn);
      __nv_bfloat16 hhv = __float2bfloat16(h);
      float hlf = h - __bfloat162float(hhv);
      *(__nv_bfloat16*)(sm + OFF_HH + (size_t)(n * HS + ut) * 2) = hhv;
      *(__nv_bfloat16*)(sm + OFF_HL + (size_t)(n * HS + ut) * 2) = __float2bfloat16(hlf);
    }
    __syncthreads();   // (1) h1(t) visible; h2 frag reads above also complete

    // ---- load h1(t) frags (cols 0-63) -> used in GEMM2 AND next GEMM1 ----
#pragma unroll
    for (int kc = 0; kc < 4; ++kc) {
      ldm4(Bh1[kc], bHH + kc * 32);
      ldm4(Bl1[kc], bHL + kc * 32);
    }

    // ===== GEMM2: gates2 = W2 * [h1(t) ; h2(t-1)] (K=128) =====
#pragma unroll
    for (int mt = 0; mt < 2; ++mt)
#pragma unroll
      for (int nt = 0; nt < 2; ++nt) {
        D[mt][nt] = make_float4(0.f,0.f,0.f,0.f);
        E[mt][nt] = make_float4(0.f,0.f,0.f,0.f);
      }
#pragma unroll
    for (int kc = 0; kc < 8; ++kc) {
      const uint32_t* bh = (kc < 4) ? Bh1[kc] : bh2[kc - 4];
      const uint32_t* bl = (kc < 4) ? Bl1[kc] : bl2[kc - 4];
#pragma unroll
      for (int mt = 0; mt < 2; ++mt) {
        uint4 ah = *(const uint4*)(sm + OFF_A2H + (size_t)(((2*w+mt)*8 + kc)*32 + lane)*16);
        uint4 al = *(const uint4*)(sm + OFF_A2L + (size_t)(((2*w+mt)*8 + kc)*32 + lane)*16);
#pragma unroll
        for (int nt = 0; nt < 2; ++nt) {
          mma_bf(D[mt][nt], ah, bh[nt*2], bh[nt*2+1]);
          mma_bf(E[mt][nt], ah, bl[nt*2], bl[nt*2+1]);
          mma_bf(E[mt][nt], al, bh[nt*2], bh[nt*2+1]);
        }
      }
    }

    // ----- act2 -----
#pragma unroll
    for (int j = 0; j < 4; ++j) {
      int nt = j >> 1, jj = j & 1;
      int n  = nt * 8 + (lane & 3) * 2 + jj;
      float gi = (jj ? D[0][nt].y + E[0][nt].y : D[0][nt].x + E[0][nt].x) + b1r[0];
      float gf = (jj ? D[0][nt].w + E[0][nt].w : D[0][nt].z + E[0][nt].z) + b1r[1];
      float gg = (jj ? D[1][nt].y + E[1][nt].y : D[1][nt].x + E[1][nt].x) + b1r[2];
      float go = (jj ? D[1][nt].w + E[1][nt].w : D[1][nt].z + E[1][nt].z) + b1r[3];
      float cn = sig_ap(gf) * c2[j] + sig_ap(gi) * tanh_ap(gg);
      c2[j] = cn;
      float h = sig_ap(go) * tanh_ap(cn);
      __nv_bfloat16 hhv = __float2bfloat16(h);
      float hlf = h - __bfloat162float(hhv);
      *(__nv_bfloat16*)(sm + OFF_HH + (size_t)(n * HS + 64 + ut) * 2) = hhv;
      *(__nv_bfloat16*)(sm + OFF_HL + (size_t)(n * HS + 64 + ut) * 2) = __float2bfloat16(hlf);
    }
    __syncthreads();   // (2) h2(t) visible for next step's h2 frag load
  }

  // ===== FC epilogue: out[b] = fcW . h2(T-1) + fcb (h2 = hh+hl) =====
  if (tid < TILE_B) {
    float acc = fcb[0];
    const __nv_bfloat16* hh = (const __nv_bfloat16*)(sm + OFF_HH);
    const __nv_bfloat16* hl = (const __nv_bfloat16*)(sm + OFF_HL);
#pragma unroll 8
    for (int u = 0; u < 64; ++u)
      acc += fcW[u] * (__bfloat162float(hh[tid * HS + 64 + u]) +
                       __bfloat162float(hl[tid * HS + 64 + u]));
    out[bBase + tid] = acc;
  }
}

extern "C" void kernel_launch(void* const* d_in, const int* in_sizes, int n_in,
                              void* d_out, int out_size) {
  (void)in_sizes; (void)n_in; (void)out_size;
  cudaFuncSetAttribute(lstm2_hmma3_kernel,
                       cudaFuncAttributeMaxDynamicSharedMemorySize, SMEM_TOTAL);
  lstm2_hmma3_kernel<<<GRID, THREADS, SMEM_TOTAL>>>(
      (const float*)d_in[0],
      (const float*)d_in[1], (const float*)d_in[2],
      (const float*)d_in[3], (const float*)d_in[4],
      (const float*)d_in[5], (const float*)d_in[6],
      (const float*)d_in[7], (const float*)d_in[8],
      (const float*)d_in[9], (const float*)d_in[10],
      (float*)d_out);
}

// round 8
// speedup vs baseline: 1.4420x; 1.0821x over previous
#include <cuda_runtime.h>
#include <cuda_bf16.h>
#include <cstdint>

namespace {
constexpr int T_STEPS = 512;
constexpr int TILE_B  = 16;
constexpr int THREADS = 256;
constexpr int GRID    = 2048 / TILE_B;

constexpr int OFF_A1H = 0;
constexpr int OFF_A1L = 32768;
constexpr int OFF_A2H = 65536;
constexpr int OFF_A2L = 131072;
constexpr int OFF_HH  = 196608;          // 16 rows * HS bf16 = 4352 B
constexpr int OFF_HL  = 196608 + 4352;
constexpr int OFF_X   = 196608 + 8704;   // 4 KB x-chunk / final fp32 h2
constexpr int SMEM_TOTAL = OFF_X + 4096; // 209408 B
constexpr int HS = 136;                  // bf16 elems per h row (conflict-free pad)

__device__ __forceinline__ uint32_t smem_u32(const void* p) {
  uint32_t a;
  asm("{ .reg .u64 t; cvta.to.shared.u64 t, %1; cvt.u32.u64 %0, t; }" : "=r"(a) : "l"(p));
  return a;
}
__device__ __forceinline__ void ldm4(uint32_t* r, uint32_t a) {
  asm volatile("ldmatrix.sync.aligned.m8n8.x4.shared.b16 {%0,%1,%2,%3}, [%4];"
               : "=r"(r[0]), "=r"(r[1]), "=r"(r[2]), "=r"(r[3]) : "r"(a));
}
__device__ __forceinline__ void mma_bf(float4& d, const uint4& a, uint32_t b0, uint32_t b1) {
  asm volatile("mma.sync.aligned.m16n8k16.row.col.f32.bf16.bf16.f32 "
               "{%0,%1,%2,%3}, {%4,%5,%6,%7}, {%8,%9}, {%0,%1,%2,%3};"
               : "+f"(d.x), "+f"(d.y), "+f"(d.z), "+f"(d.w)
               : "r"(a.x), "r"(a.y), "r"(a.z), "r"(a.w), "r"(b0), "r"(b1));
}
__device__ __forceinline__ uint32_t pkbf2(float lo, float hi) {
  __nv_bfloat16 l = __float2bfloat16(lo), h = __float2bfloat16(hi);
  unsigned short ls, hs;
  memcpy(&ls, &l, 2); memcpy(&hs, &h, 2);
  return (uint32_t)ls | ((uint32_t)hs << 16);
}
__device__ __forceinline__ float tanh_ap(float x) {
  float y; asm("tanh.approx.f32 %0, %1;" : "=f"(y) : "f"(x)); return y;
}
__device__ __forceinline__ float sig_ap(float x) {
  return fmaf(tanh_ap(0.5f * x), 0.5f, 0.5f);
}
}  // namespace

__global__ void __launch_bounds__(THREADS, 1) lstm2_hmma5_kernel(
    const float* __restrict__ x,
    const float* __restrict__ Wih0, const float* __restrict__ Whh0,
    const float* __restrict__ bih0, const float* __restrict__ bhh0,
    const float* __restrict__ Wih1, const float* __restrict__ Whh1,
    const float* __restrict__ bih1, const float* __restrict__ bhh1,
    const float* __restrict__ fcW,  const float* __restrict__ fcb,
    float* __restrict__ out)
{
  extern __shared__ char sm[];
  const uint32_t sb = smem_u32(sm);
  const int tid = threadIdx.x, w = tid >> 5, lane = tid & 31;
  const int bBase = blockIdx.x * TILE_B;

  // ---- build A fragments (per-lane mma layout, wh/wl split), row perm:
  // mma-row R -> gate g=(R&31)>>3, unit u=(R>>5)*8+(R&7) ----
  for (int i = tid; i < 64 * 32; i += THREADS) {
    int f = i >> 5, l = i & 31;
    int mt = f >> 2, kc = f & 3;
    int p = l >> 2, c0 = (l & 3) * 2;
    float wh[8], wl[8];
#pragma unroll
    for (int e = 0; e < 8; ++e) {
      int R = mt * 16 + p + ((e >> 1) & 1) * 8;
      int k = kc * 16 + c0 + (e & 1) + (e >> 2) * 8;
      int g = (R & 31) >> 3, u = (R >> 5) * 8 + (R & 7);
      float wv = Whh0[(g * 64 + u) * 64 + k];
      __nv_bfloat16 b = __float2bfloat16(wv);
      wh[e] = __bfloat162float(b); wl[e] = wv - wh[e];
    }
    *(uint4*)(sm + OFF_A1H + (size_t)i * 16) =
        make_uint4(pkbf2(wh[0],wh[1]), pkbf2(wh[2],wh[3]), pkbf2(wh[4],wh[5]), pkbf2(wh[6],wh[7]));
    *(uint4*)(sm + OFF_A1L + (size_t)i * 16) =
        make_uint4(pkbf2(wl[0],wl[1]), pkbf2(wl[2],wl[3]), pkbf2(wl[4],wl[5]), pkbf2(wl[6],wl[7]));
  }
  for (int i = tid; i < 128 * 32; i += THREADS) {
    int f = i >> 5, l = i & 31;
    int mt = f >> 3, kc = f & 7;
    int p = l >> 2, c0 = (l & 3) * 2;
    float wh[8], wl[8];
#pragma unroll
    for (int e = 0; e < 8; ++e) {
      int R = mt * 16 + p + ((e >> 1) & 1) * 8;
      int k = kc * 16 + c0 + (e & 1) + (e >> 2) * 8;
      int g = (R & 31) >> 3, u = (R >> 5) * 8 + (R & 7);
      float wv = (k < 64) ? Wih1[(g * 64 + u) * 64 + k]
                          : Whh1[(g * 64 + u) * 64 + (k - 64)];
      __nv_bfloat16 b = __float2bfloat16(wv);
      wh[e] = __bfloat162float(b); wl[e] = wv - wh[e];
    }
    *(uint4*)(sm + OFF_A2H + (size_t)i * 16) =
        make_uint4(pkbf2(wh[0],wh[1]), pkbf2(wh[2],wh[3]), pkbf2(wh[4],wh[5]), pkbf2(wh[6],wh[7]));
    *(uint4*)(sm + OFF_A2L + (size_t)i * 16) =
        make_uint4(pkbf2(wl[0],wl[1]), pkbf2(wl[2],wl[3]), pkbf2(wl[4],wl[5]), pkbf2(wl[6],wl[7]));
  }
  // zero h buffers (hh + hl contiguous: 2*4352 B)
  for (int i = tid; i < 2176; i += THREADS)
    reinterpret_cast<uint32_t*>(sm + OFF_HH)[i] = 0u;

  // per-thread act constants: unit ut, batches n = nt*8 + (lane&3)*2 + jj
  const int ut = w * 8 + (lane >> 2);
  float wxr[4], b0r[4], b1r[4];
#pragma unroll
  for (int g = 0; g < 4; ++g) {
    wxr[g] = Wih0[g * 64 + ut];
    b0r[g] = bih0[g * 64 + ut] + bhh0[g * 64 + ut];
    b1r[g] = bih1[g * 64 + ut] + bhh1[g * 64 + ut];
  }
  // ldmatrix per-lane base: tile ti: n=((ti>>1)&1)*8+(lane&7), k=(ti&1)*8
  const int ti = lane >> 3;
  const uint32_t boff = (uint32_t)((((ti >> 1) & 1) * 8 + (lane & 7)) * HS + (ti & 1) * 8) * 2;
  const uint32_t bHH = sb + OFF_HH + boff;
  const uint32_t bHL = sb + OFF_HL + boff;

  float* xb = reinterpret_cast<float*>(sm + OFF_X);
  float c1[4] = {0.f,0.f,0.f,0.f}, c2[4] = {0.f,0.f,0.f,0.f};

  // resident h1 fragments (h1(-1) = 0)
  uint32_t Bh1[4][4], Bl1[4][4];
#pragma unroll
  for (int kc = 0; kc < 4; ++kc)
#pragma unroll
    for (int r = 0; r < 4; ++r) { Bh1[kc][r] = 0u; Bl1[kc][r] = 0u; }

  __syncthreads();

  for (int t = 0; t < T_STEPS; ++t) {
    if ((t & 63) == 0) {
      int b16 = tid >> 4, tq = tid & 15;
      float4 v = *reinterpret_cast<const float4*>(
          x + (size_t)(bBase + b16) * T_STEPS + t + tq * 4);
      xb[(tq * 4 + 0) * 16 + b16] = v.x;
      xb[(tq * 4 + 1) * 16 + b16] = v.y;
      xb[(tq * 4 + 2) * 16 + b16] = v.z;
      xb[(tq * 4 + 3) * 16 + b16] = v.w;
      __syncthreads();
    }

    // ---- load h2(t-1) frags (cols 64-127); disjoint from act1's writes ----
    uint32_t bh2[4][4], bl2[4][4];
#pragma unroll
    for (int kc = 0; kc < 4; ++kc) {
      ldm4(bh2[kc], bHH + 128 + kc * 32);
      ldm4(bl2[kc], bHL + 128 + kc * 32);
    }

    // ===== Phase A =====
    // GEMM1: gates1 = W1 * h1(t-1)  (resident frags)
    float4 D1[2][2], E1[2][2], D2[2][2], E2[2][2];
#pragma unroll
    for (int mt = 0; mt < 2; ++mt)
#pragma unroll
      for (int nt = 0; nt < 2; ++nt) {
        D1[mt][nt] = make_float4(0.f,0.f,0.f,0.f);
        E1[mt][nt] = make_float4(0.f,0.f,0.f,0.f);
        D2[mt][nt] = make_float4(0.f,0.f,0.f,0.f);
        E2[mt][nt] = make_float4(0.f,0.f,0.f,0.f);
      }
#pragma unroll
    for (int kc = 0; kc < 4; ++kc)
#pragma unroll
      for (int mt = 0; mt < 2; ++mt) {
        uint4 ah = *(const uint4*)(sm + OFF_A1H + (size_t)(((2*w+mt)*4 + kc)*32 + lane)*16);
        uint4 al = *(const uint4*)(sm + OFF_A1L + (size_t)(((2*w+mt)*4 + kc)*32 + lane)*16);
#pragma unroll
        for (int nt = 0; nt < 2; ++nt) {
          mma_bf(D1[mt][nt], ah, Bh1[kc][nt*2], Bh1[kc][nt*2+1]);
          mma_bf(E1[mt][nt], ah, Bl1[kc][nt*2], Bl1[kc][nt*2+1]);
          mma_bf(E1[mt][nt], al, Bh1[kc][nt*2], Bh1[kc][nt*2+1]);
        }
      }
    // GEMM2b: Whh1 * h2(t-1)  (kc 4-7 of A2) — independent of act1
#pragma unroll
    for (int kc = 0; kc < 4; ++kc)
#pragma unroll
      for (int mt = 0; mt < 2; ++mt) {
        uint4 ah = *(const uint4*)(sm + OFF_A2H + (size_t)(((2*w+mt)*8 + 4 + kc)*32 + lane)*16);
        uint4 al = *(const uint4*)(sm + OFF_A2L + (size_t)(((2*w+mt)*8 + 4 + kc)*32 + lane)*16);
#pragma unroll
        for (int nt = 0; nt < 2; ++nt) {
          mma_bf(D2[mt][nt], ah, bh2[kc][nt*2], bh2[kc][nt*2+1]);
          mma_bf(E2[mt][nt], ah, bl2[kc][nt*2], bl2[kc][nt*2+1]);
          mma_bf(E2[mt][nt], al, bh2[kc][nt*2], bh2[kc][nt*2+1]);
        }
      }

    // ----- act1 (overlaps GEMM2b tensor stream) -----
#pragma unroll
    for (int j = 0; j < 4; ++j) {
      int nt = j >> 1, jj = j & 1;
      int n  = nt * 8 + (lane & 3) * 2 + jj;
      float xv = xb[(t & 63) * 16 + n];
      float gi = (jj ? D1[0][nt].y + E1[0][nt].y : D1[0][nt].x + E1[0][nt].x) + b0r[0] + wxr[0] * xv;
      float gf = (jj ? D1[0][nt].w + E1[0][nt].w : D1[0][nt].z + E1[0][nt].z) + b0r[1] + wxr[1] * xv;
      float gg = (jj ? D1[1][nt].y + E1[1][nt].y : D1[1][nt].x + E1[1][nt].x) + b0r[2] + wxr[2] * xv;
      float go = (jj ? D1[1][nt].w + E1[1][nt].w : D1[1][nt].z + E1[1][nt].z) + b0r[3] + wxr[3] * xv;
      float cn = sig_ap(gf) * c1[j] + sig_ap(gi) * tanh_ap(gg);
      c1[j] = cn;
      float h = sig_ap(go) * tanh_ap(cn);
      __nv_bfloat16 hhv = __float2bfloat16(h);
      float hlf = h - __bfloat162float(hhv);
      *(__nv_bfloat16*)(sm + OFF_HH + (size_t)(n * HS + ut) * 2) = hhv;
      *(__nv_bfloat16*)(sm + OFF_HL + (size_t)(n * HS + ut) * 2) = __float2bfloat16(hlf);
    }
    __syncthreads();   // (1) h1(t) visible; h2 frag reads above complete

    // ===== Phase B =====
    // load h1(t) frags (cols 0-63) -> GEMM2a now, GEMM1 next step
#pragma unroll
    for (int kc = 0; kc < 4; ++kc) {
      ldm4(Bh1[kc], bHH + kc * 32);
      ldm4(Bl1[kc], bHL + kc * 32);
    }
    // GEMM2a: Wih1 * h1(t)  (kc 0-3 of A2), accumulate into D2/E2
#pragma unroll
    for (int kc = 0; kc < 4; ++kc)
#pragma unroll
      for (int mt = 0; mt < 2; ++mt) {
        uint4 ah = *(const uint4*)(sm + OFF_A2H + (size_t)(((2*w+mt)*8 + kc)*32 + lane)*16);
        uint4 al = *(const uint4*)(sm + OFF_A2L + (size_t)(((2*w+mt)*8 + kc)*32 + lane)*16);
#pragma unroll
        for (int nt = 0; nt < 2; ++nt) {
          mma_bf(D2[mt][nt], ah, Bh1[kc][nt*2], Bh1[kc][nt*2+1]);
          mma_bf(E2[mt][nt], ah, Bl1[kc][nt*2], Bl1[kc][nt*2+1]);
          mma_bf(E2[mt][nt], al, Bh1[kc][nt*2], Bh1[kc][nt*2+1]);
        }
      }

    // ----- act2 -----
#pragma unroll
    for (int j = 0; j < 4; ++j) {
      int nt = j >> 1, jj = j & 1;
      int n  = nt * 8 + (lane & 3) * 2 + jj;
      float gi = (jj ? D2[0][nt].y + E2[0][nt].y : D2[0][nt].x + E2[0][nt].x) + b1r[0];
      float gf = (jj ? D2[0][nt].w + E2[0][nt].w : D2[0][nt].z + E2[0][nt].z) + b1r[1];
      float gg = (jj ? D2[1][nt].y + E2[1][nt].y : D2[1][nt].x + E2[1][nt].x) + b1r[2];
      float go = (jj ? D2[1][nt].w + E2[1][nt].w : D2[1][nt].z + E2[1][nt].z) + b1r[3];
      float cn = sig_ap(gf) * c2[j] + sig_ap(gi) * tanh_ap(gg);
      c2[j] = cn;
      float h = sig_ap(go) * tanh_ap(cn);
      __nv_bfloat16 hhv = __float2bfloat16(h);
      float hlf = h - __bfloat162float(hhv);
      *(__nv_bfloat16*)(sm + OFF_HH + (size_t)(n * HS + 64 + ut) * 2) = hhv;
      *(__nv_bfloat16*)(sm + OFF_HL + (size_t)(n * HS + 64 + ut) * 2) = __float2bfloat16(hlf);
      if (t == T_STEPS - 1) xb[ut * 16 + n] = h;   // exact fp32 h2(T-1) for FC
    }
    __syncthreads();   // (2) h2(t) visible for next step's frag load
  }

  // ===== FC epilogue: out[b] = fcW . h2(T-1) + fcb  (exact fp32 h2) =====
  if (tid < TILE_B) {
    float acc = fcb[0];
#pragma unroll 8
    for (int u = 0; u < 64; ++u)
      acc += fcW[u] * xb[u * 16 + tid];
    out[bBase + tid] = acc;
  }
}

extern "C" void kernel_launch(void* const* d_in, const int* in_sizes, int n_in,
                              void* d_out, int out_size) {
  (void)in_sizes; (void)n_in; (void)out_size;
  cudaFuncSetAttribute(lstm2_hmma5_kernel,
                       cudaFuncAttributeMaxDynamicSharedMemorySize, SMEM_TOTAL);
  lstm2_hmma5_kernel<<<GRID, THREADS, SMEM_TOTAL>>>(
      (const float*)d_in[0],
      (const float*)d_in[1], (const float*)d_in[2],
      (const float*)d_in[3], (const float*)d_in[4],
      (const float*)d_in[5], (const float*)d_in[6],
      (const float*)d_in[7], (const float*)d_in[8],
      (const float*)d_in[9], (const float*)d_in[10],
      (float*)d_out);
}

// round 9
// speedup vs baseline: 1.8848x; 1.3071x over previous
#include <cuda_runtime.h>
#include <cuda_fp16.h>
#include <cstdint>

namespace {
constexpr int T_STEPS = 512;
constexpr int TILE_B  = 16;
constexpr int THREADS = 256;
constexpr int GRID    = 2048 / TILE_B;

constexpr int OFF_A1H = 0;
constexpr int OFF_A1L = 32768;
constexpr int OFF_A2H = 65536;
constexpr int OFF_A2L = 131072;
constexpr int OFF_HH  = 196608;          // 16 rows * HS fp16 = 4352 B
constexpr int OFF_X   = 196608 + 4352;   // 4 KB x-chunk / final fp32 h2
constexpr int SMEM_TOTAL = OFF_X + 4096; // 205056 B
constexpr int HS = 136;                  // fp16 elems per h row (conflict-free pad)

__device__ __forceinline__ uint32_t smem_u32(const void* p) {
  uint32_t a;
  asm("{ .reg .u64 t; cvta.to.shared.u64 t, %1; cvt.u32.u64 %0, t; }" : "=r"(a) : "l"(p));
  return a;
}
__device__ __forceinline__ void ldm4(uint32_t* r, uint32_t a) {
  asm volatile("ldmatrix.sync.aligned.m8n8.x4.shared.b16 {%0,%1,%2,%3}, [%4];"
               : "=r"(r[0]), "=r"(r[1]), "=r"(r[2]), "=r"(r[3]) : "r"(a));
}
__device__ __forceinline__ void mma_hf(float4& d, const uint4& a, uint32_t b0, uint32_t b1) {
  asm volatile("mma.sync.aligned.m16n8k16.row.col.f32.f16.f16.f32 "
               "{%0,%1,%2,%3}, {%4,%5,%6,%7}, {%8,%9}, {%0,%1,%2,%3};"
               : "+f"(d.x), "+f"(d.y), "+f"(d.z), "+f"(d.w)
               : "r"(a.x), "r"(a.y), "r"(a.z), "r"(a.w), "r"(b0), "r"(b1));
}
__device__ __forceinline__ uint32_t pkhf2(float lo, float hi) {
  __half l = __float2half_rn(lo), h = __float2half_rn(hi);
  unsigned short ls, hs;
  memcpy(&ls, &l, 2); memcpy(&hs, &h, 2);
  return (uint32_t)ls | ((uint32_t)hs << 16);
}
__device__ __forceinline__ float tanh_ap(float x) {
  float y; asm("tanh.approx.f32 %0, %1;" : "=f"(y) : "f"(x)); return y;
}
__device__ __forceinline__ float sig_ap(float x) {
  return fmaf(tanh_ap(0.5f * x), 0.5f, 0.5f);
}
}  // namespace

__global__ void __launch_bounds__(THREADS, 1) lstm2_hmma6_kernel(
    const float* __restrict__ x,
    const float* __restrict__ Wih0, const float* __restrict__ Whh0,
    const float* __restrict__ bih0, const float* __restrict__ bhh0,
    const float* __restrict__ Wih1, const float* __restrict__ Whh1,
    const float* __restrict__ bih1, const float* __restrict__ bhh1,
    const float* __restrict__ fcW,  const float* __restrict__ fcb,
    float* __restrict__ out)
{
  extern __shared__ char sm[];
  const uint32_t sb = smem_u32(sm);
  const int tid = threadIdx.x, w = tid >> 5, lane = tid & 31;
  const int bBase = blockIdx.x * TILE_B;

  // ---- build A fragments (per-lane mma layout, wh/wl fp16 split), row perm:
  // mma-row R -> gate g=(R&31)>>3, unit u=(R>>5)*8+(R&7) ----
  for (int i = tid; i < 64 * 32; i += THREADS) {
    int f = i >> 5, l = i & 31;
    int mt = f >> 2, kc = f & 3;
    int p = l >> 2, c0 = (l & 3) * 2;
    float wh[8], wl[8];
#pragma unroll
    for (int e = 0; e < 8; ++e) {
      int R = mt * 16 + p + ((e >> 1) & 1) * 8;
      int k = kc * 16 + c0 + (e & 1) + (e >> 2) * 8;
      int g = (R & 31) >> 3, u = (R >> 5) * 8 + (R & 7);
      float wv = Whh0[(g * 64 + u) * 64 + k];
      __half b = __float2half_rn(wv);
      wh[e] = __half2float(b); wl[e] = wv - wh[e];
    }
    *(uint4*)(sm + OFF_A1H + (size_t)i * 16) =
        make_uint4(pkhf2(wh[0],wh[1]), pkhf2(wh[2],wh[3]), pkhf2(wh[4],wh[5]), pkhf2(wh[6],wh[7]));
    *(uint4*)(sm + OFF_A1L + (size_t)i * 16) =
        make_uint4(pkhf2(wl[0],wl[1]), pkhf2(wl[2],wl[3]), pkhf2(wl[4],wl[5]), pkhf2(wl[6],wl[7]));
  }
  for (int i = tid; i < 128 * 32; i += THREADS) {
    int f = i >> 5, l = i & 31;
    int mt = f >> 3, kc = f & 7;
    int p = l >> 2, c0 = (l & 3) * 2;
    float wh[8], wl[8];
#pragma unroll
    for (int e = 0; e < 8; ++e) {
      int R = mt * 16 + p + ((e >> 1) & 1) * 8;
      int k = kc * 16 + c0 + (e & 1) + (e >> 2) * 8;
      int g = (R & 31) >> 3, u = (R >> 5) * 8 + (R & 7);
      float wv = (k < 64) ? Wih1[(g * 64 + u) * 64 + k]
                          : Whh1[(g * 64 + u) * 64 + (k - 64)];
      __half b = __float2half_rn(wv);
      wh[e] = __half2float(b); wl[e] = wv - wh[e];
    }
    *(uint4*)(sm + OFF_A2H + (size_t)i * 16) =
        make_uint4(pkhf2(wh[0],wh[1]), pkhf2(wh[2],wh[3]), pkhf2(wh[4],wh[5]), pkhf2(wh[6],wh[7]));
    *(uint4*)(sm + OFF_A2L + (size_t)i * 16) =
        make_uint4(pkhf2(wl[0],wl[1]), pkhf2(wl[2],wl[3]), pkhf2(wl[4],wl[5]), pkhf2(wl[6],wl[7]));
  }
  // zero h buffer
  for (int i = tid; i < 1088; i += THREADS)
    reinterpret_cast<uint32_t*>(sm + OFF_HH)[i] = 0u;

  // per-thread act constants: unit ut, batches n = nt*8 + (lane&3)*2 + jj
  const int ut = w * 8 + (lane >> 2);
  float wxr[4], b0r[4], b1r[4];
#pragma unroll
  for (int g = 0; g < 4; ++g) {
    wxr[g] = Wih0[g * 64 + ut];
    b0r[g] = bih0[g * 64 + ut] + bhh0[g * 64 + ut];
    b1r[g] = bih1[g * 64 + ut] + bhh1[g * 64 + ut];
  }
  // ldmatrix per-lane base: tile ti: n=((ti>>1)&1)*8+(lane&7), k=(ti&1)*8
  const int ti = lane >> 3;
  const uint32_t boff = (uint32_t)((((ti >> 1) & 1) * 8 + (lane & 7)) * HS + (ti & 1) * 8) * 2;
  const uint32_t bHH = sb + OFF_HH + boff;

  float* xb = reinterpret_cast<float*>(sm + OFF_X);
  float c1[4] = {0.f,0.f,0.f,0.f}, c2[4] = {0.f,0.f,0.f,0.f};

  __syncthreads();

  // ---- A1 fragments register-resident (loop-invariant) ----
  uint4 a1h[2][4], a1l[2][4];
#pragma unroll
  for (int mt = 0; mt < 2; ++mt)
#pragma unroll
    for (int kc = 0; kc < 4; ++kc) {
      a1h[mt][kc] = *(const uint4*)(sm + OFF_A1H + (size_t)(((2*w+mt)*4 + kc)*32 + lane)*16);
      a1l[mt][kc] = *(const uint4*)(sm + OFF_A1L + (size_t)(((2*w+mt)*4 + kc)*32 + lane)*16);
    }

  // resident h1 fragments (h1(-1) = 0)
  uint32_t Bh1[4][4];
#pragma unroll
  for (int kc = 0; kc < 4; ++kc)
#pragma unroll
    for (int r = 0; r < 4; ++r) Bh1[kc][r] = 0u;

  for (int t = 0; t < T_STEPS; ++t) {
    if ((t & 63) == 0) {
      int b16 = tid >> 4, tq = tid & 15;
      float4 v = *reinterpret_cast<const float4*>(
          x + (size_t)(bBase + b16) * T_STEPS + t + tq * 4);
      xb[(tq * 4 + 0) * 16 + b16] = v.x;
      xb[(tq * 4 + 1) * 16 + b16] = v.y;
      xb[(tq * 4 + 2) * 16 + b16] = v.z;
      xb[(tq * 4 + 3) * 16 + b16] = v.w;
      __syncthreads();
    }

    // ---- load h2(t-1) frags (cols 64-127); disjoint from act1's writes ----
    uint32_t bh2[4][4];
#pragma unroll
    for (int kc = 0; kc < 4; ++kc) ldm4(bh2[kc], bHH + 128 + kc * 32);

    // ===== Phase A: GEMM1 + GEMM2b (both depend only on t-1 state) =====
    float4 D1[2][2], E1[2][2], D2[2][2], E2[2][2];
#pragma unroll
    for (int mt = 0; mt < 2; ++mt)
#pragma unroll
      for (int nt = 0; nt < 2; ++nt) {
        D1[mt][nt] = make_float4(0.f,0.f,0.f,0.f);
        E1[mt][nt] = make_float4(0.f,0.f,0.f,0.f);
        D2[mt][nt] = make_float4(0.f,0.f,0.f,0.f);
        E2[mt][nt] = make_float4(0.f,0.f,0.f,0.f);
      }
    // GEMM1: gates1 = W1 * h1(t-1)  (resident A1, resident Bh1)
#pragma unroll
    for (int kc = 0; kc < 4; ++kc)
#pragma unroll
      for (int mt = 0; mt < 2; ++mt)
#pragma unroll
        for (int nt = 0; nt < 2; ++nt) {
          mma_hf(D1[mt][nt], a1h[mt][kc], Bh1[kc][nt*2], Bh1[kc][nt*2+1]);
          mma_hf(E1[mt][nt], a1l[mt][kc], Bh1[kc][nt*2], Bh1[kc][nt*2+1]);
        }
    // GEMM2b: Whh1 * h2(t-1)  (kc 4-7 of A2)
#pragma unroll
    for (int kc = 0; kc < 4; ++kc)
#pragma unroll
      for (int mt = 0; mt < 2; ++mt) {
        uint4 ah = *(const uint4*)(sm + OFF_A2H + (size_t)(((2*w+mt)*8 + 4 + kc)*32 + lane)*16);
        uint4 al = *(const uint4*)(sm + OFF_A2L + (size_t)(((2*w+mt)*8 + 4 + kc)*32 + lane)*16);
#pragma unroll
        for (int nt = 0; nt < 2; ++nt) {
          mma_hf(D2[mt][nt], ah, bh2[kc][nt*2], bh2[kc][nt*2+1]);
          mma_hf(E2[mt][nt], al, bh2[kc][nt*2], bh2[kc][nt*2+1]);
        }
      }

    // ----- act1 (overlaps GEMM2b tensor stream) -----
#pragma unroll
    for (int j = 0; j < 4; ++j) {
      int nt = j >> 1, jj = j & 1;
      int n  = nt * 8 + (lane & 3) * 2 + jj;
      float xv = xb[(t & 63) * 16 + n];
      float gi = (jj ? D1[0][nt].y + E1[0][nt].y : D1[0][nt].x + E1[0][nt].x) + b0r[0] + wxr[0] * xv;
      float gf = (jj ? D1[0][nt].w + E1[0][nt].w : D1[0][nt].z + E1[0][nt].z) + b0r[1] + wxr[1] * xv;
      float gg = (jj ? D1[1][nt].y + E1[1][nt].y : D1[1][nt].x + E1[1][nt].x) + b0r[2] + wxr[2] * xv;
      float go = (jj ? D1[1][nt].w + E1[1][nt].w : D1[1][nt].z + E1[1][nt].z) + b0r[3] + wxr[3] * xv;
      float cn = sig_ap(gf) * c1[j] + sig_ap(gi) * tanh_ap(gg);
      c1[j] = cn;
      float h = sig_ap(go) * tanh_ap(cn);
      *(__half*)(sm + OFF_HH + (size_t)(n * HS + ut) * 2) = __float2half_rn(h);
    }
    __syncthreads();   // (1) h1(t) visible; h2 frag reads above complete

    // ===== Phase B =====
#pragma unroll
    for (int kc = 0; kc < 4; ++kc) ldm4(Bh1[kc], bHH + kc * 32);
    // GEMM2a: Wih1 * h1(t)  (kc 0-3 of A2), accumulate into D2/E2
#pragma unroll
    for (int kc = 0; kc < 4; ++kc)
#pragma unroll
      for (int mt = 0; mt < 2; ++mt) {
        uint4 ah = *(const uint4*)(sm + OFF_A2H + (size_t)(((2*w+mt)*8 + kc)*32 + lane)*16);
        uint4 al = *(const uint4*)(sm + OFF_A2L + (size_t)(((2*w+mt)*8 + kc)*32 + lane)*16);
#pragma unroll
        for (int nt = 0; nt < 2; ++nt) {
          mma_hf(D2[mt][nt], ah, Bh1[kc][nt*2], Bh1[kc][nt*2+1]);
          mma_hf(E2[mt][nt], al, Bh1[kc][nt*2], Bh1[kc][nt*2+1]);
        }
      }

    // ----- act2 -----
#pragma unroll
    for (int j = 0; j < 4; ++j) {
      int nt = j >> 1, jj = j & 1;
      int n  = nt * 8 + (lane & 3) * 2 + jj;
      float gi = (jj ? D2[0][nt].y + E2[0][nt].y : D2[0][nt].x + E2[0][nt].x) + b1r[0];
      float gf = (jj ? D2[0][nt].w + E2[0][nt].w : D2[0][nt].z + E2[0][nt].z) + b1r[1];
      float gg = (jj ? D2[1][nt].y + E2[1][nt].y : D2[1][nt].x + E2[1][nt].x) + b1r[2];
      float go = (jj ? D2[1][nt].w + E2[1][nt].w : D2[1][nt].z + E2[1][nt].z) + b1r[3];
      float cn = sig_ap(gf) * c2[j] + sig_ap(gi) * tanh_ap(gg);
      c2[j] = cn;
      float h = sig_ap(go) * tanh_ap(cn);
      *(__half*)(sm + OFF_HH + (size_t)(n * HS + 64 + ut) * 2) = __float2half_rn(h);
      if (t == T_STEPS - 1) xb[ut * 16 + n] = h;   // exact fp32 h2(T-1) for FC
    }
    __syncthreads();   // (2) h2(t) visible for next step's frag load
  }

  // ===== FC epilogue: out[b] = fcW . h2(T-1) + fcb  (exact fp32 h2) =====
  if (tid < TILE_B) {
    float acc = fcb[0];
#pragma unroll 8
    for (int u = 0; u < 64; ++u)
      acc += fcW[u] * xb[u * 16 + tid];
    out[bBase + tid] = acc;
  }
}

extern "C" void kernel_launch(void* const* d_in, const int* in_sizes, int n_in,
                              void* d_out, int out_size) {
  (void)in_sizes; (void)n_in; (void)out_size;
  cudaFuncSetAttribute(lstm2_hmma6_kernel,
                       cudaFuncAttributeMaxDynamicSharedMemorySize, SMEM_TOTAL);
  lstm2_hmma6_kernel<<<GRID, THREADS, SMEM_TOTAL>>>(
      (const float*)d_in[0],
      (const float*)d_in[1], (const float*)d_in[2],
      (const float*)d_in[3], (const float*)d_in[4],
      (const float*)d_in[5], (const float*)d_in[6],
      (const float*)d_in[7], (const float*)d_in[8],
      (const float*)d_in[9], (const float*)d_in[10],
      (float*)d_out);
}

// round 10
// speedup vs baseline: 2.8692x; 1.5223x over previous
#include <cuda_runtime.h>
#include <cuda_fp16.h>
#include <cstdint>

namespace {
constexpr int T_STEPS = 512;
constexpr int TILE_B  = 16;
constexpr int THREADS = 256;
constexpr int GRID    = 2048 / TILE_B;

constexpr int OFF_A1  = 0;               // 64 frags * 512B = 32768
constexpr int OFF_A2  = 32768;           // 128 frags * 512B = 65536
constexpr int OFF_HH  = 98304;           // 16 rows * HS fp16 = 4352 B
constexpr int OFF_X   = 98304 + 4352;    // 4 KB x-chunk / final fp32 h2
constexpr int SMEM_TOTAL = OFF_X + 4096; // 106752 B
constexpr int HS = 136;                  // fp16 elems per h row (conflict-free pad)

__device__ __forceinline__ uint32_t smem_u32(const void* p) {
  uint32_t a;
  asm("{ .reg .u64 t; cvta.to.shared.u64 t, %1; cvt.u32.u64 %0, t; }" : "=r"(a) : "l"(p));
  return a;
}
__device__ __forceinline__ void ldm4(uint32_t* r, uint32_t a) {
  asm volatile("ldmatrix.sync.aligned.m8n8.x4.shared.b16 {%0,%1,%2,%3}, [%4];"
               : "=r"(r[0]), "=r"(r[1]), "=r"(r[2]), "=r"(r[3]) : "r"(a));
}
__device__ __forceinline__ void mma_hf(float4& d, const uint4& a, uint32_t b0, uint32_t b1) {
  asm volatile("mma.sync.aligned.m16n8k16.row.col.f32.f16.f16.f32 "
               "{%0,%1,%2,%3}, {%4,%5,%6,%7}, {%8,%9}, {%0,%1,%2,%3};"
               : "+f"(d.x), "+f"(d.y), "+f"(d.z), "+f"(d.w)
               : "r"(a.x), "r"(a.y), "r"(a.z), "r"(a.w), "r"(b0), "r"(b1));
}
__device__ __forceinline__ uint32_t pkhf2(float lo, float hi) {
  __half l = __float2half_rn(lo), h = __float2half_rn(hi);
  unsigned short ls, hs;
  memcpy(&ls, &l, 2); memcpy(&hs, &h, 2);
  return (uint32_t)ls | ((uint32_t)hs << 16);
}
__device__ __forceinline__ float tanh_ap(float x) {
  float y; asm("tanh.approx.f32 %0, %1;" : "=f"(y) : "f"(x)); return y;
}
__device__ __forceinline__ float sig_ap(float x) {
  return fmaf(tanh_ap(0.5f * x), 0.5f, 0.5f);
}
}  // namespace

__global__ void __launch_bounds__(THREADS, 1) lstm2_hmma7_kernel(
    const float* __restrict__ x,
    const float* __restrict__ Wih0, const float* __restrict__ Whh0,
    const float* __restrict__ bih0, const float* __restrict__ bhh0,
    const float* __restrict__ Wih1, const float* __restrict__ Whh1,
    const float* __restrict__ bih1, const float* __restrict__ bhh1,
    const float* __restrict__ fcW,  const float* __restrict__ fcb,
    float* __restrict__ out)
{
  extern __shared__ char sm[];
  const uint32_t sb = smem_u32(sm);
  const int tid = threadIdx.x, w = tid >> 5, lane = tid & 31;
  const int bBase = blockIdx.x * TILE_B;

  // ---- build A fragments (per-lane mma layout, single fp16), row perm:
  // mma-row R -> gate g=(R&31)>>3, unit u=(R>>5)*8+(R&7) ----
  for (int i = tid; i < 64 * 32; i += THREADS) {
    int f = i >> 5, l = i & 31;
    int mt = f >> 2, kc = f & 3;
    int p = l >> 2, c0 = (l & 3) * 2;
    float wv[8];
#pragma unroll
    for (int e = 0; e < 8; ++e) {
      int R = mt * 16 + p + ((e >> 1) & 1) * 8;
      int k = kc * 16 + c0 + (e & 1) + (e >> 2) * 8;
      int g = (R & 31) >> 3, u = (R >> 5) * 8 + (R & 7);
      wv[e] = Whh0[(g * 64 + u) * 64 + k];
    }
    *(uint4*)(sm + OFF_A1 + (size_t)i * 16) =
        make_uint4(pkhf2(wv[0],wv[1]), pkhf2(wv[2],wv[3]),
                   pkhf2(wv[4],wv[5]), pkhf2(wv[6],wv[7]));
  }
  for (int i = tid; i < 128 * 32; i += THREADS) {
    int f = i >> 5, l = i & 31;
    int mt = f >> 3, kc = f & 7;
    int p = l >> 2, c0 = (l & 3) * 2;
    float wv[8];
#pragma unroll
    for (int e = 0; e < 8; ++e) {
      int R = mt * 16 + p + ((e >> 1) & 1) * 8;
      int k = kc * 16 + c0 + (e & 1) + (e >> 2) * 8;
      int g = (R & 31) >> 3, u = (R >> 5) * 8 + (R & 7);
      wv[e] = (k < 64) ? Wih1[(g * 64 + u) * 64 + k]
                       : Whh1[(g * 64 + u) * 64 + (k - 64)];
    }
    *(uint4*)(sm + OFF_A2 + (size_t)i * 16) =
        make_uint4(pkhf2(wv[0],wv[1]), pkhf2(wv[2],wv[3]),
                   pkhf2(wv[4],wv[5]), pkhf2(wv[6],wv[7]));
  }
  // zero h buffer
  for (int i = tid; i < 1088; i += THREADS)
    reinterpret_cast<uint32_t*>(sm + OFF_HH)[i] = 0u;

  // per-thread act constants: unit ut, batches n = nt*8 + (lane&3)*2 + jj
  const int ut = w * 8 + (lane >> 2);
  float wxr[4], b0r[4], b1r[4];
#pragma unroll
  for (int g = 0; g < 4; ++g) {
    wxr[g] = Wih0[g * 64 + ut];
    b0r[g] = bih0[g * 64 + ut] + bhh0[g * 64 + ut];
    b1r[g] = bih1[g * 64 + ut] + bhh1[g * 64 + ut];
  }
  // ldmatrix per-lane base: tile ti: n=((ti>>1)&1)*8+(lane&7), k=(ti&1)*8
  const int ti = lane >> 3;
  const uint32_t boff = (uint32_t)((((ti >> 1) & 1) * 8 + (lane & 7)) * HS + (ti & 1) * 8) * 2;
  const uint32_t bHH = sb + OFF_HH + boff;

  float* xb = reinterpret_cast<float*>(sm + OFF_X);
  float c1[4] = {0.f,0.f,0.f,0.f}, c2[4] = {0.f,0.f,0.f,0.f};

  __syncthreads();

  // ---- A1 fragments register-resident (loop-invariant) ----
  uint4 a1[2][4];
#pragma unroll
  for (int mt = 0; mt < 2; ++mt)
#pragma unroll
    for (int kc = 0; kc < 4; ++kc)
      a1[mt][kc] = *(const uint4*)(sm + OFF_A1 + (size_t)(((2*w+mt)*4 + kc)*32 + lane)*16);

  // resident h1 fragments (h1(-1) = 0)
  uint32_t Bh1[4][4];
#pragma unroll
  for (int kc = 0; kc < 4; ++kc)
#pragma unroll
    for (int r = 0; r < 4; ++r) Bh1[kc][r] = 0u;

  for (int t = 0; t < T_STEPS; ++t) {
    if ((t & 63) == 0) {
      int b16 = tid >> 4, tq = tid & 15;
      float4 v = *reinterpret_cast<const float4*>(
          x + (size_t)(bBase + b16) * T_STEPS + t + tq * 4);
      xb[(tq * 4 + 0) * 16 + b16] = v.x;
      xb[(tq * 4 + 1) * 16 + b16] = v.y;
      xb[(tq * 4 + 2) * 16 + b16] = v.z;
      xb[(tq * 4 + 3) * 16 + b16] = v.w;
      __syncthreads();
    }

    // ---- load h2(t-1) frags (cols 64-127); disjoint from act1's writes ----
    uint32_t bh2[4][4];
#pragma unroll
    for (int kc = 0; kc < 4; ++kc) ldm4(bh2[kc], bHH + 128 + kc * 32);

    // ===== Phase A: GEMM1 + GEMM2b (both depend only on t-1 state) =====
    float4 D1[2][2], D2[2][2];
#pragma unroll
    for (int mt = 0; mt < 2; ++mt)
#pragma unroll
      for (int nt = 0; nt < 2; ++nt) {
        D1[mt][nt] = make_float4(0.f,0.f,0.f,0.f);
        D2[mt][nt] = make_float4(0.f,0.f,0.f,0.f);
      }
    // GEMM1: gates1 = W1 * h1(t-1)  (resident A1, resident Bh1)
#pragma unroll
    for (int kc = 0; kc < 4; ++kc)
#pragma unroll
      for (int mt = 0; mt < 2; ++mt)
#pragma unroll
        for (int nt = 0; nt < 2; ++nt)
          mma_hf(D1[mt][nt], a1[mt][kc], Bh1[kc][nt*2], Bh1[kc][nt*2+1]);
    // GEMM2b: Whh1 * h2(t-1)  (kc 4-7 of A2)
#pragma unroll
    for (int kc = 0; kc < 4; ++kc)
#pragma unroll
      for (int mt = 0; mt < 2; ++mt) {
        uint4 ah = *(const uint4*)(sm + OFF_A2 + (size_t)(((2*w+mt)*8 + 4 + kc)*32 + lane)*16);
#pragma unroll
        for (int nt = 0; nt < 2; ++nt)
          mma_hf(D2[mt][nt], ah, bh2[kc][nt*2], bh2[kc][nt*2+1]);
      }

    // ----- act1 (overlaps GEMM2b tensor stream) -----
#pragma unroll
    for (int j = 0; j < 4; ++j) {
      int nt = j >> 1, jj = j & 1;
      int n  = nt * 8 + (lane & 3) * 2 + jj;
      float xv = xb[(t & 63) * 16 + n];
      float gi = (jj ? D1[0][nt].y : D1[0][nt].x) + b0r[0] + wxr[0] * xv;
      float gf = (jj ? D1[0][nt].w : D1[0][nt].z) + b0r[1] + wxr[1] * xv;
      float gg = (jj ? D1[1][nt].y : D1[1][nt].x) + b0r[2] + wxr[2] * xv;
      float go = (jj ? D1[1][nt].w : D1[1][nt].z) + b0r[3] + wxr[3] * xv;
      float cn = sig_ap(gf) * c1[j] + sig_ap(gi) * tanh_ap(gg);
      c1[j] = cn;
      float h = sig_ap(go) * tanh_ap(cn);
      *(__half*)(sm + OFF_HH + (size_t)(n * HS + ut) * 2) = __float2half_rn(h);
    }
    __syncthreads();   // (1) h1(t) visible; h2 frag reads above complete

    // ===== Phase B =====
#pragma unroll
    for (int kc = 0; kc < 4; ++kc) ldm4(Bh1[kc], bHH + kc * 32);
    // GEMM2a: Wih1 * h1(t)  (kc 0-3 of A2), accumulate into D2
#pragma unroll
    for (int kc = 0; kc < 4; ++kc)
#pragma unroll
      for (int mt = 0; mt < 2; ++mt) {
        uint4 ah = *(const uint4*)(sm + OFF_A2 + (size_t)(((2*w+mt)*8 + kc)*32 + lane)*16);
#pragma unroll
        for (int nt = 0; nt < 2; ++nt)
          mma_hf(D2[mt][nt], ah, Bh1[kc][nt*2], Bh1[kc][nt*2+1]);
      }

    // ----- act2 -----
#pragma unroll
    for (int j = 0; j < 4; ++j) {
      int nt = j >> 1, jj = j & 1;
      int n  = nt * 8 + (lane & 3) * 2 + jj;
      float gi = (jj ? D2[0][nt].y : D2[0][nt].x) + b1r[0];
      float gf = (jj ? D2[0][nt].w : D2[0][nt].z) + b1r[1];
      float gg = (jj ? D2[1][nt].y : D2[1][nt].x) + b1r[2];
      float go = (jj ? D2[1][nt].w : D2[1][nt].z) + b1r[3];
      float cn = sig_ap(gf) * c2[j] + sig_ap(gi) * tanh_ap(gg);
      c2[j] = cn;
      float h = sig_ap(go) * tanh_ap(cn);
      *(__half*)(sm + OFF_HH + (size_t)(n * HS + 64 + ut) * 2) = __float2half_rn(h);
      if (t == T_STEPS - 1) xb[ut * 16 + n] = h;   // exact fp32 h2(T-1) for FC
    }
    __syncthreads();   // (2) h2(t) visible for next step's frag load
  }

  // ===== FC epilogue: out[b] = fcW . h2(T-1) + fcb  (exact fp32 h2) =====
  if (tid < TILE_B) {
    float acc = fcb[0];
#pragma unroll 8
    for (int u = 0; u < 64; ++u)
      acc += fcW[u] * xb[u * 16 + tid];
    out[bBase + tid] = acc;
  }
}

extern "C" void kernel_launch(void* const* d_in, const int* in_sizes, int n_in,
                              void* d_out, int out_size) {
  (void)in_sizes; (void)n_in; (void)out_size;
  cudaFuncSetAttribute(lstm2_hmma7_kernel,
                       cudaFuncAttributeMaxDynamicSharedMemorySize, SMEM_TOTAL);
  lstm2_hmma7_kernel<<<GRID, THREADS, SMEM_TOTAL>>>(
      (const float*)d_in[0],
      (const float*)d_in[1], (const float*)d_in[2],
      (const float*)d_in[3], (const float*)d_in[4],
      (const float*)d_in[5], (const float*)d_in[6],
      (const float*)d_in[7], (const float*)d_in[8],
      (const float*)d_in[9], (const float*)d_in[10],
      (float*)d_out);
}

// round 11
// speedup vs baseline: 3.5346x; 1.2319x over previous
#include <cuda_runtime.h>
#include <cuda_fp16.h>
#include <cstdint>

namespace {
constexpr int T_STEPS = 512;
constexpr int TILE_B  = 16;
constexpr int THREADS = 256;
constexpr int GRID    = 2048 / TILE_B;

constexpr int OFF_A1  = 0;               // 64 frags * 512B = 32768
constexpr int OFF_A2  = 32768;           // 128 frags * 512B = 65536
constexpr int OFF_HH  = 98304;           // 16 rows * HS fp16 = 4352 B
constexpr int OFF_X   = 98304 + 4352;    // 4 KB x-chunk / final fp32 h2
constexpr int SMEM_TOTAL = OFF_X + 4096; // 106752 B
constexpr int HS = 136;                  // fp16 elems per h row (conflict-free pad)

__device__ __forceinline__ uint32_t smem_u32(const void* p) {
  uint32_t a;
  asm("{ .reg .u64 t; cvta.to.shared.u64 t, %1; cvt.u32.u64 %0, t; }" : "=r"(a) : "l"(p));
  return a;
}
__device__ __forceinline__ void ldm4(uint32_t* r, uint32_t a) {
  asm volatile("ldmatrix.sync.aligned.m8n8.x4.shared.b16 {%0,%1,%2,%3}, [%4];"
               : "=r"(r[0]), "=r"(r[1]), "=r"(r[2]), "=r"(r[3]) : "r"(a));
}
__device__ __forceinline__ void mma_hf(float4& d, const uint4& a, uint32_t b0, uint32_t b1) {
  asm volatile("mma.sync.aligned.m16n8k16.row.col.f32.f16.f16.f32 "
               "{%0,%1,%2,%3}, {%4,%5,%6,%7}, {%8,%9}, {%0,%1,%2,%3};"
               : "+f"(d.x), "+f"(d.y), "+f"(d.z), "+f"(d.w)
               : "r"(a.x), "r"(a.y), "r"(a.z), "r"(a.w), "r"(b0), "r"(b1));
}
__device__ __forceinline__ uint32_t pkhf2(float lo, float hi) {
  __half l = __float2half_rn(lo), h = __float2half_rn(hi);
  unsigned short ls, hs;
  memcpy(&ls, &l, 2); memcpy(&hs, &h, 2);
  return (uint32_t)ls | ((uint32_t)hs << 16);
}
__device__ __forceinline__ float tanh_ap(float x) {
  float y; asm("tanh.approx.f32 %0, %1;" : "=f"(y) : "f"(x)); return y;
}
__device__ __forceinline__ float sig_ap(float x) {
  return fmaf(tanh_ap(0.5f * x), 0.5f, 0.5f);
}
}  // namespace

__global__ void __launch_bounds__(THREADS, 1) lstm2_hmma8_kernel(
    const float* __restrict__ x,
    const float* __restrict__ Wih0, const float* __restrict__ Whh0,
    const float* __restrict__ bih0, const float* __restrict__ bhh0,
    const float* __restrict__ Wih1, const float* __restrict__ Whh1,
    const float* __restrict__ bih1, const float* __restrict__ bhh1,
    const float* __restrict__ fcW,  const float* __restrict__ fcb,
    float* __restrict__ out)
{
  extern __shared__ char sm[];
  const uint32_t sb = smem_u32(sm);
  const int tid = threadIdx.x, w = tid >> 5, lane = tid & 31;
  const int bBase = blockIdx.x * TILE_B;

  // ---- build A fragments (per-lane mma layout, single fp16), row perm:
  // mma-row R -> gate g=(R&31)>>3, unit u=(R>>5)*8+(R&7) ----
  for (int i = tid; i < 64 * 32; i += THREADS) {
    int f = i >> 5, l = i & 31;
    int mt = f >> 2, kc = f & 3;
    int p = l >> 2, c0 = (l & 3) * 2;
    float wv[8];
#pragma unroll
    for (int e = 0; e < 8; ++e) {
      int R = mt * 16 + p + ((e >> 1) & 1) * 8;
      int k = kc * 16 + c0 + (e & 1) + (e >> 2) * 8;
      int g = (R & 31) >> 3, u = (R >> 5) * 8 + (R & 7);
      wv[e] = Whh0[(g * 64 + u) * 64 + k];
    }
    *(uint4*)(sm + OFF_A1 + (size_t)i * 16) =
        make_uint4(pkhf2(wv[0],wv[1]), pkhf2(wv[2],wv[3]),
                   pkhf2(wv[4],wv[5]), pkhf2(wv[6],wv[7]));
  }
  for (int i = tid; i < 128 * 32; i += THREADS) {
    int f = i >> 5, l = i & 31;
    int mt = f >> 3, kc = f & 7;
    int p = l >> 2, c0 = (l & 3) * 2;
    float wv[8];
#pragma unroll
    for (int e = 0; e < 8; ++e) {
      int R = mt * 16 + p + ((e >> 1) & 1) * 8;
      int k = kc * 16 + c0 + (e & 1) + (e >> 2) * 8;
      int g = (R & 31) >> 3, u = (R >> 5) * 8 + (R & 7);
      wv[e] = (k < 64) ? Wih1[(g * 64 + u) * 64 + k]
                       : Whh1[(g * 64 + u) * 64 + (k - 64)];
    }
    *(uint4*)(sm + OFF_A2 + (size_t)i * 16) =
        make_uint4(pkhf2(wv[0],wv[1]), pkhf2(wv[2],wv[3]),
                   pkhf2(wv[4],wv[5]), pkhf2(wv[6],wv[7]));
  }
  // zero h buffer
  for (int i = tid; i < 1088; i += THREADS)
    reinterpret_cast<uint32_t*>(sm + OFF_HH)[i] = 0u;

  // per-thread act constants: unit ut, batches n = nt*8 + (lane&3)*2 + jj
  const int ut = w * 8 + (lane >> 2);
  float wxr[4], b0r[4], b1r[4];
#pragma unroll
  for (int g = 0; g < 4; ++g) {
    wxr[g] = Wih0[g * 64 + ut];
    b0r[g] = bih0[g * 64 + ut] + bhh0[g * 64 + ut];
    b1r[g] = bih1[g * 64 + ut] + bhh1[g * 64 + ut];
  }
  // ldmatrix per-lane base: tile ti: n=((ti>>1)&1)*8+(lane&7), k=(ti&1)*8
  const int ti = lane >> 3;
  const uint32_t boff = (uint32_t)((((ti >> 1) & 1) * 8 + (lane & 7)) * HS + (ti & 1) * 8) * 2;
  const uint32_t bHH = sb + OFF_HH + boff;

  float* xb = reinterpret_cast<float*>(sm + OFF_X);
  float c1[4] = {0.f,0.f,0.f,0.f}, c2[4] = {0.f,0.f,0.f,0.f};

  __syncthreads();

  // ---- A1 + A2 fragments register-resident (loop-invariant) ----
  uint4 a1[2][4], a2[2][8];
#pragma unroll
  for (int mt = 0; mt < 2; ++mt) {
#pragma unroll
    for (int kc = 0; kc < 4; ++kc)
      a1[mt][kc] = *(const uint4*)(sm + OFF_A1 + (size_t)(((2*w+mt)*4 + kc)*32 + lane)*16);
#pragma unroll
    for (int kc = 0; kc < 8; ++kc)
      a2[mt][kc] = *(const uint4*)(sm + OFF_A2 + (size_t)(((2*w+mt)*8 + kc)*32 + lane)*16);
  }

  // resident h1 fragments (h1(-1) = 0) and retimed gates1 accumulator
  uint32_t Bh1[4][4];
#pragma unroll
  for (int kc = 0; kc < 4; ++kc)
#pragma unroll
    for (int r = 0; r < 4; ++r) Bh1[kc][r] = 0u;
  float4 D1[2][2];   // gates1(t) = W1*h1(t-1); computed in prev iter's Phase B
#pragma unroll
  for (int mt = 0; mt < 2; ++mt)
#pragma unroll
    for (int nt = 0; nt < 2; ++nt) D1[mt][nt] = make_float4(0.f,0.f,0.f,0.f);

  for (int t = 0; t < T_STEPS; ++t) {
    if ((t & 63) == 0) {
      int b16 = tid >> 4, tq = tid & 15;
      float4 v = *reinterpret_cast<const float4*>(
          x + (size_t)(bBase + b16) * T_STEPS + t + tq * 4);
      xb[(tq * 4 + 0) * 16 + b16] = v.x;
      xb[(tq * 4 + 1) * 16 + b16] = v.y;
      xb[(tq * 4 + 2) * 16 + b16] = v.z;
      xb[(tq * 4 + 3) * 16 + b16] = v.w;
      __syncthreads();
    }

    // ===== Phase A: GEMM2b (tensor) overlapped with act1 (MUFU) =====
    uint32_t bh2[4][4];
#pragma unroll
    for (int kc = 0; kc < 4; ++kc) ldm4(bh2[kc], bHH + 128 + kc * 32);

    float4 D2[2][2];
#pragma unroll
    for (int mt = 0; mt < 2; ++mt)
#pragma unroll
      for (int nt = 0; nt < 2; ++nt) D2[mt][nt] = make_float4(0.f,0.f,0.f,0.f);
    // GEMM2b: Whh1 * h2(t-1)  (kc 4-7 of A2, register-resident)
#pragma unroll
    for (int kc = 0; kc < 4; ++kc)
#pragma unroll
      for (int mt = 0; mt < 2; ++mt)
#pragma unroll
        for (int nt = 0; nt < 2; ++nt)
          mma_hf(D2[mt][nt], a2[mt][4 + kc], bh2[kc][nt*2], bh2[kc][nt*2+1]);

    // act1: D1 is ready (computed last iter) -> overlaps GEMM2b in flight
#pragma unroll
    for (int j = 0; j < 4; ++j) {
      int nt = j >> 1, jj = j & 1;
      int n  = nt * 8 + (lane & 3) * 2 + jj;
      float xv = xb[(t & 63) * 16 + n];
      float gi = (jj ? D1[0][nt].y : D1[0][nt].x) + b0r[0] + wxr[0] * xv;
      float gf = (jj ? D1[0][nt].w : D1[0][nt].z) + b0r[1] + wxr[1] * xv;
      float gg = (jj ? D1[1][nt].y : D1[1][nt].x) + b0r[2] + wxr[2] * xv;
      float go = (jj ? D1[1][nt].w : D1[1][nt].z) + b0r[3] + wxr[3] * xv;
      float cn = sig_ap(gf) * c1[j] + sig_ap(gi) * tanh_ap(gg);
      c1[j] = cn;
      float h = sig_ap(go) * tanh_ap(cn);
      *(__half*)(sm + OFF_HH + (size_t)(n * HS + ut) * 2) = __float2half_rn(h);
    }
    __syncthreads();   // (1) h1(t) visible; bh2 reads complete before act2 writes

    // ===== Phase B: GEMM2a -> GEMM1(t+1) (tensor) overlapped with act2 =====
#pragma unroll
    for (int kc = 0; kc < 4; ++kc) ldm4(Bh1[kc], bHH + kc * 32);
    // GEMM2a: Wih1 * h1(t)  (kc 0-3 of A2), completes D2
#pragma unroll
    for (int kc = 0; kc < 4; ++kc)
#pragma unroll
      for (int mt = 0; mt < 2; ++mt)
#pragma unroll
        for (int nt = 0; nt < 2; ++nt)
          mma_hf(D2[mt][nt], a2[mt][kc], Bh1[kc][nt*2], Bh1[kc][nt*2+1]);
    // GEMM1 (retimed): gates1(t+1) = W1 * h1(t) — independent of act2
#pragma unroll
    for (int mt = 0; mt < 2; ++mt)
#pragma unroll
      for (int nt = 0; nt < 2; ++nt) D1[mt][nt] = make_float4(0.f,0.f,0.f,0.f);
#pragma unroll
    for (int kc = 0; kc < 4; ++kc)
#pragma unroll
      for (int mt = 0; mt < 2; ++mt)
#pragma unroll
        for (int nt = 0; nt < 2; ++nt)
          mma_hf(D1[mt][nt], a1[mt][kc], Bh1[kc][nt*2], Bh1[kc][nt*2+1]);

    // act2: waits only on D2 (issued first) -> overlaps GEMM1 in flight
#pragma unroll
    for (int j = 0; j < 4; ++j) {
      int nt = j >> 1, jj = j & 1;
      int n  = nt * 8 + (lane & 3) * 2 + jj;
      float gi = (jj ? D2[0][nt].y : D2[0][nt].x) + b1r[0];
      float gf = (jj ? D2[0][nt].w : D2[0][nt].z) + b1r[1];
      float gg = (jj ? D2[1][nt].y : D2[1][nt].x) + b1r[2];
      float go = (jj ? D2[1][nt].w : D2[1][nt].z) + b1r[3];
      float cn = sig_ap(gf) * c2[j] + sig_ap(gi) * tanh_ap(gg);
      c2[j] = cn;
      float h = sig_ap(go) * tanh_ap(cn);
      *(__half*)(sm + OFF_HH + (size_t)(n * HS + 64 + ut) * 2) = __float2half_rn(h);
      if (t == T_STEPS - 1) xb[ut * 16 + n] = h;   // exact fp32 h2(T-1) for FC
    }
    __syncthreads();   // (2) h2(t) visible for next step's bh2 load
  }

  // ===== FC epilogue: out[b] = fcW . h2(T-1) + fcb  (exact fp32 h2) =====
  if (tid < TILE_B) {
    float acc = fcb[0];
#pragma unroll 8
    for (int u = 0; u < 64; ++u)
      acc += fcW[u] * xb[u * 16 + tid];
    out[bBase + tid] = acc;
  }
}

extern "C" void kernel_launch(void* const* d_in, const int* in_sizes, int n_in,
                              void* d_out, int out_size) {
  (void)in_sizes; (void)n_in; (void)out_size;
  cudaFuncSetAttribute(lstm2_hmma8_kernel,
                       cudaFuncAttributeMaxDynamicSharedMemorySize, SMEM_TOTAL);
  lstm2_hmma8_kernel<<<GRID, THREADS, SMEM_TOTAL>>>(
      (const float*)d_in[0],
      (const float*)d_in[1], (const float*)d_in[2],
      (const float*)d_in[3], (const float*)d_in[4],
      (const float*)d_in[5], (const float*)d_in[6],
      (const float*)d_in[7], (const float*)d_in[8],
      (const float*)d_in[9], (const float*)d_in[10],
      (float*)d_out);
}